// round 4
// baseline (speedup 1.0000x reference)
#include <cuda_runtime.h>
#include <cuda_fp16.h>
#include <cstdint>

// ---------------- problem constants ----------------
#define NSZ      1024
#define M_TOTAL  32768

// GEMM tiling
#define BM 128
#define BN 128
#define BK 64                       // halves per K chunk (128 bytes per smem row)
#define STG 3
#define NKC (NSZ / BK)              // 16 K-chunks
#define ROWB 128                    // bytes per smem row
#define A_BYTES (BM * ROWB)         // 16384
#define B_BYTES (BN * ROWB)         // 16384
#define STAGE_B (A_BYTES + B_BYTES) // 32768
#define SMEM_TOTAL (STG * STAGE_B)  // 98304

// ---------------- scratch (no allocation allowed) ----------------
__device__ __align__(1024) __half g_xh[(size_t)M_TOTAL * NSZ];   // 64 MiB fp16 x
__device__ __align__(1024) __half g_wh[NSZ * NSZ];               // 2 MiB fp16 W
__device__ float g_av[2][NSZ];
__device__ float g_bv[2][NSZ];

// ---------------- helpers ----------------
__device__ __forceinline__ uint32_t smem_u32(const void* p) {
    uint32_t a;
    asm("{ .reg .u64 t; cvta.to.shared.u64 t, %1; cvt.u32.u64 %0, t; }" : "=r"(a) : "l"(p));
    return a;
}
__device__ __forceinline__ uint32_t swz(uint32_t o) {       // 128B swizzle
    return o ^ ((o >> 3) & 0x70);
}
__device__ __forceinline__ void cp_async16(uint32_t saddr, const void* gaddr) {
    asm volatile("cp.async.cg.shared.global [%0], [%1], 16;" :: "r"(saddr), "l"(gaddr));
}
__device__ __forceinline__ void ldsm_x4(uint32_t* r, uint32_t addr) {
    asm volatile("ldmatrix.sync.aligned.m8n8.x4.shared.b16 {%0,%1,%2,%3}, [%4];"
                 : "=r"(r[0]), "=r"(r[1]), "=r"(r[2]), "=r"(r[3]) : "r"(addr));
}
__device__ __forceinline__ void ldsm_x2(uint32_t* r, uint32_t addr) {
    asm volatile("ldmatrix.sync.aligned.m8n8.x2.shared.b16 {%0,%1}, [%2];"
                 : "=r"(r[0]), "=r"(r[1]) : "r"(addr));
}
__device__ __forceinline__ void mma16816(float* d, const uint32_t* a, const uint32_t* b) {
    asm volatile(
        "mma.sync.aligned.m16n8k16.row.col.f32.f16.f16.f32 "
        "{%0,%1,%2,%3}, {%4,%5,%6,%7}, {%8,%9}, {%0,%1,%2,%3};"
        : "+f"(d[0]), "+f"(d[1]), "+f"(d[2]), "+f"(d[3])
        : "r"(a[0]), "r"(a[1]), "r"(a[2]), "r"(a[3]), "r"(b[0]), "r"(b[1]));
}

// ---------------- kernel 1: x fp32 -> fp16 ----------------
__global__ void xconv_kernel(const float4* __restrict__ x, uint2* __restrict__ xh) {
    int i = blockIdx.x * blockDim.x + threadIdx.x;
    float4 f = x[i];
    __half2 h0 = __floats2half2_rn(f.x, f.y);
    __half2 h1 = __floats2half2_rn(f.z, f.w);
    uint2 u;
    u.x = *reinterpret_cast<uint32_t*>(&h0);
    u.y = *reinterpret_cast<uint32_t*>(&h1);
    xh[i] = u;
}

// ---------------- kernel 2: sinkhorn vector iteration ----------------
__global__ void sinkhorn_init_kernel() {
    int t = threadIdx.x;
    g_av[0][t] = 0.f; g_bv[0][t] = 0.f;
}

__global__ void sinkhorn_step_kernel(const float* __restrict__ w, int src) {
    // grid 32 CTAs x 512 threads. L0 = w * 8 (1/TEMP).
    __shared__ float sm_m[16][32];
    __shared__ float sm_s[16][32];
    const int b = blockIdx.x;
    const int tid = threadIdx.x;
    const int wid = tid >> 5, lid = tid & 31;
    const int dst = src ^ 1;
    const float invT = 8.0f;
    const float* aold = g_av[src];
    const float* bold = g_bv[src];

    // rows: warp wid handles rows 32*b + 2*wid + {0,1}
    #pragma unroll
    for (int rr = 0; rr < 2; rr++) {
        int row = 32 * b + 2 * wid + rr;
        const float* wr = w + (size_t)row * NSZ;
        float v[32];
        float m = -1e30f;
        #pragma unroll
        for (int j = 0; j < 32; j++) {
            v[j] = wr[lid + 32 * j] * invT - bold[lid + 32 * j];
            m = fmaxf(m, v[j]);
        }
        #pragma unroll
        for (int off = 16; off > 0; off >>= 1)
            m = fmaxf(m, __shfl_xor_sync(0xffffffffu, m, off));
        float s = 0.f;
        #pragma unroll
        for (int j = 0; j < 32; j++) s += __expf(v[j] - m);
        #pragma unroll
        for (int off = 16; off > 0; off >>= 1)
            s += __shfl_xor_sync(0xffffffffu, s, off);
        if (lid == 0)
            g_av[dst][row] = 0.5f * aold[row] + 0.5f * (m + logf(s));
    }

    // cols: warp wid handles rows [64*wid, 64*wid+64), column 32*b + lane
    {
        int col = 32 * b + lid;
        const float* wp = w + (size_t)(64 * wid) * NSZ + col;
        float m = -1e30f, s = 0.f;
        for (int i = 0; i < 64; i++) {
            float v = wp[(size_t)i * NSZ] * invT - aold[64 * wid + i];
            if (v > m) { s = s * __expf(m - v) + 1.0f; m = v; }
            else       { s += __expf(v - m); }
        }
        sm_m[wid][lid] = m; sm_s[wid][lid] = s;
    }
    __syncthreads();
    if (wid == 0) {
        int col = 32 * b + lid;
        float M = -1e30f;
        #pragma unroll
        for (int k = 0; k < 16; k++) M = fmaxf(M, sm_m[k][lid]);
        float S = 0.f;
        #pragma unroll
        for (int k = 0; k < 16; k++) S += sm_s[k][lid] * __expf(sm_m[k][lid] - M);
        g_bv[dst][col] = 0.5f * bold[col] + 0.5f * (M + logf(S));
    }
}

// ---------------- kernel 3: W = exp(L0 - a - b) -> fp16 ----------------
__global__ void wconv_kernel(const float* __restrict__ w, __half* __restrict__ wh) {
    int idx = blockIdx.x * blockDim.x + threadIdx.x;  // 1M threads
    int o = idx >> 10, d = idx & 1023;
    float lp = w[idx] * 8.0f - g_av[0][o] - g_bv[0][d];
    wh[idx] = __float2half(__expf(lp));
}

// ---------------- kernel 4: HMMA fp16 GEMM  y = x @ W^T ----------------
// A = g_xh [M, K] K-contig, B = g_wh [N, K] K-contig, out fp32 [M, N].
__device__ __forceinline__ void load_stage(uint32_t sbase, const __half* __restrict__ A,
                                           const __half* __restrict__ B,
                                           int m_base, int n_base, int kc, int tid) {
    const uint32_t sA = sbase, sB = sbase + A_BYTES;
    const __half* ga = A + (size_t)m_base * NSZ + kc * BK;
    const __half* gb = B + (size_t)n_base * NSZ + kc * BK;
    #pragma unroll
    for (int i = 0; i < 4; i++) {
        int id = tid + i * 256;
        int row = id >> 3, c = id & 7;
        cp_async16(sA + swz(row * ROWB + c * 16), ga + row * NSZ + c * 8);
    }
    #pragma unroll
    for (int i = 0; i < 4; i++) {
        int id = tid + i * 256;
        int row = id >> 3, c = id & 7;
        cp_async16(sB + swz(row * ROWB + c * 16), gb + row * NSZ + c * 8);
    }
}

__global__ void __launch_bounds__(256, 2) gemm_kernel(
    const __half* __restrict__ A, const __half* __restrict__ B,
    float* __restrict__ out)
{
    extern __shared__ __align__(1024) char smem[];
    const uint32_t sb = smem_u32(smem);
    const int tid = threadIdx.x;
    const int lane = tid & 31;
    const int w = tid >> 5;
    const int wm = w >> 2;          // 0..1  -> M offset wm*64
    const int wn = w & 3;           // 0..3  -> N offset wn*32
    const int n_base = blockIdx.x * BN;
    const int m_base = blockIdx.y * BM;

    float acc[4][4][4];
    #pragma unroll
    for (int i = 0; i < 4; i++)
        #pragma unroll
        for (int j = 0; j < 4; j++)
            #pragma unroll
            for (int q = 0; q < 4; q++) acc[i][j][q] = 0.f;

    // per-lane ldmatrix byte offsets (pre-swizzle)
    const uint32_t aRow = (uint32_t)(wm * 64 + (lane & 15)) * ROWB + ((lane >> 4) * 16);
    const uint32_t bRow = (uint32_t)(wn * 32 + (lane & 7)) * ROWB + (((lane >> 3) & 1) * 16);

    // prologue: stages 0,1
    load_stage(sb + 0 * STAGE_B, A, B, m_base, n_base, 0, tid);
    asm volatile("cp.async.commit_group;" ::: "memory");
    load_stage(sb + 1 * STAGE_B, A, B, m_base, n_base, 1, tid);
    asm volatile("cp.async.commit_group;" ::: "memory");

    int buf = 0;
    #pragma unroll 1
    for (int kc = 0; kc < NKC; kc++) {
        asm volatile("cp.async.wait_group 1;" ::: "memory");
        __syncthreads();

        // issue next chunk (into the buffer computed two iters ago)
        if (kc + 2 < NKC) {
            int nb = buf + 2; if (nb >= STG) nb -= STG;
            load_stage(sb + nb * STAGE_B, A, B, m_base, n_base, kc + 2, tid);
        }
        asm volatile("cp.async.commit_group;" ::: "memory");

        const uint32_t sA = sb + buf * STAGE_B;
        const uint32_t sB = sA + A_BYTES;
        #pragma unroll
        for (int ks = 0; ks < 4; ks++) {
            uint32_t af[4][4], bf[4][2];
            #pragma unroll
            for (int mt = 0; mt < 4; mt++)
                ldsm_x4(af[mt], sA + swz(aRow + (uint32_t)mt * 16 * ROWB + ks * 32));
            #pragma unroll
            for (int nt = 0; nt < 4; nt++)
                ldsm_x2(bf[nt], sB + swz(bRow + (uint32_t)nt * 8 * ROWB + ks * 32));
            #pragma unroll
            for (int mt = 0; mt < 4; mt++)
                #pragma unroll
                for (int nt = 0; nt < 4; nt++)
                    mma16816(acc[mt][nt], af[mt], bf[nt]);
        }
        buf++; if (buf >= STG) buf = 0;
    }

    // epilogue: direct fp32 stores
    const int r0 = m_base + wm * 64 + (lane >> 2);
    const int c0 = n_base + wn * 32 + (lane & 3) * 2;
    #pragma unroll
    for (int mt = 0; mt < 4; mt++) {
        #pragma unroll
        for (int nt = 0; nt < 4; nt++) {
            float* p0 = out + (size_t)(r0 + mt * 16) * NSZ + c0 + nt * 8;
            float* p1 = out + (size_t)(r0 + mt * 16 + 8) * NSZ + c0 + nt * 8;
            *reinterpret_cast<float2*>(p0) = make_float2(acc[mt][nt][0], acc[mt][nt][1]);
            *reinterpret_cast<float2*>(p1) = make_float2(acc[mt][nt][2], acc[mt][nt][3]);
        }
    }
}

// ---------------- host ----------------
extern "C" void kernel_launch(void* const* d_in, const int* in_sizes, int n_in,
                              void* d_out, int out_size) {
    const float* x = (const float*)d_in[0];
    const float* w = (const float*)d_in[1];
    if (in_sizes[0] == NSZ * NSZ && in_sizes[1] != NSZ * NSZ) {  // defensive ordering
        x = (const float*)d_in[1];
        w = (const float*)d_in[0];
    }
    float* out = (float*)d_out;

    void* xh_ptr = nullptr;
    void* wh_ptr = nullptr;
    cudaGetSymbolAddress(&xh_ptr, g_xh);
    cudaGetSymbolAddress(&wh_ptr, g_wh);

    cudaFuncSetAttribute(gemm_kernel, cudaFuncAttributeMaxDynamicSharedMemorySize, SMEM_TOTAL);

    // 1) convert x to fp16
    xconv_kernel<<<(M_TOTAL * NSZ / 4) / 256, 256>>>((const float4*)x, (uint2*)xh_ptr);

    // 2) sinkhorn on (a,b) vectors
    sinkhorn_init_kernel<<<1, 1024>>>();
    for (int i = 0; i < 10; i++)
        sinkhorn_step_kernel<<<32, 512>>>(w, i & 1);

    // 3) W = exp(w/T - a - b) in fp16
    wconv_kernel<<<(NSZ * NSZ) / 256, 256>>>(w, (__half*)wh_ptr);

    // 4) GEMM
    gemm_kernel<<<dim3(NSZ / BN, M_TOTAL / BM, 1), 256, SMEM_TOTAL>>>(
        (const __half*)xh_ptr, (const __half*)wh_ptr, out);
}

// round 5
// speedup vs baseline: 1.1041x; 1.1041x over previous
#include <cuda_runtime.h>
#include <cuda_fp16.h>
#include <cstdint>

// ---------------- problem constants ----------------
#define NSZ      1024
#define M_TOTAL  32768

// GEMM tiling
#define BM 128
#define BN 128
#define BK 64                       // halves per K chunk (128 bytes per smem row)
#define STG 3
#define NKC (NSZ / BK)              // 16 K-chunks
#define ROWB 128                    // bytes per smem row
#define A_BYTES (BM * ROWB)         // 16384
#define B_BYTES (BN * ROWB)         // 16384
#define STAGE_B (A_BYTES + B_BYTES) // 32768
#define SMEM_TOTAL (STG * STAGE_B)  // 98304

// sinkhorn persistent kernel
#define SCTA 128                    // CTAs (<=148, co-resident)
#define STHR 512
#define ROWS_PER (NSZ / SCTA)       // 8
#define N_ITER 10

// ---------------- scratch (no allocation allowed) ----------------
__device__ __align__(1024) __half g_xh[(size_t)M_TOTAL * NSZ];   // 64 MiB fp16 x
__device__ __align__(1024) __half g_wh[NSZ * NSZ];               // 2 MiB fp16 W
__device__ __align__(1024) float  g_E[NSZ * NSZ];                // 4 MiB exp(W/T)
__device__ float g_u[NSZ];
__device__ float g_v[NSZ];
__device__ float g_cpart[SCTA][NSZ];                             // 512 KiB col partials
__device__ int          g_bar_cnt;
__device__ volatile int g_bar_gen;

// ---------------- helpers ----------------
__device__ __forceinline__ uint32_t smem_u32(const void* p) {
    uint32_t a;
    asm("{ .reg .u64 t; cvta.to.shared.u64 t, %1; cvt.u32.u64 %0, t; }" : "=r"(a) : "l"(p));
    return a;
}
__device__ __forceinline__ uint32_t swz(uint32_t o) {       // 128B swizzle
    return o ^ ((o >> 3) & 0x70);
}
__device__ __forceinline__ void cp_async16(uint32_t saddr, const void* gaddr) {
    asm volatile("cp.async.cg.shared.global [%0], [%1], 16;" :: "r"(saddr), "l"(gaddr));
}
__device__ __forceinline__ void ldsm_x4(uint32_t* r, uint32_t addr) {
    asm volatile("ldmatrix.sync.aligned.m8n8.x4.shared.b16 {%0,%1,%2,%3}, [%4];"
                 : "=r"(r[0]), "=r"(r[1]), "=r"(r[2]), "=r"(r[3]) : "r"(addr));
}
__device__ __forceinline__ void ldsm_x2(uint32_t* r, uint32_t addr) {
    asm volatile("ldmatrix.sync.aligned.m8n8.x2.shared.b16 {%0,%1}, [%2];"
                 : "=r"(r[0]), "=r"(r[1]) : "r"(addr));
}
__device__ __forceinline__ void mma16816(float* d, const uint32_t* a, const uint32_t* b) {
    asm volatile(
        "mma.sync.aligned.m16n8k16.row.col.f32.f16.f16.f32 "
        "{%0,%1,%2,%3}, {%4,%5,%6,%7}, {%8,%9}, {%0,%1,%2,%3};"
        : "+f"(d[0]), "+f"(d[1]), "+f"(d[2]), "+f"(d[3])
        : "r"(a[0]), "r"(a[1]), "r"(a[2]), "r"(a[3]), "r"(b[0]), "r"(b[1]));
}

// grid-wide barrier (sense reversal, persistent grid of SCTA CTAs).
// __threadfence (gpu scope) emits CCTL.IVALL -> L1D invalidated, so
// post-barrier plain loads observe other CTAs' writes.
__device__ __forceinline__ void grid_barrier() {
    __syncthreads();
    if (threadIdx.x == 0) {
        int gen = g_bar_gen;
        __threadfence();                       // drain my writes to L2
        if (atomicAdd(&g_bar_cnt, 1) == SCTA - 1) {
            atomicExch(&g_bar_cnt, 0);
            __threadfence();
            g_bar_gen = gen + 1;
        } else {
            while (g_bar_gen == gen) { __nanosleep(64); }
        }
        __threadfence();                       // invalidate L1 before reads
    }
    __syncthreads();
}

// exp with cheap polynomial for tiny args (off-diagonal entries are ~1e-4)
__device__ __forceinline__ float exp_mixed(float x) {
    if (fabsf(x) < 0.125f) {
        // 1 + x + x^2/2 + x^3/6 + x^4/24 ; |err| < 3e-8 at 0.125
        float p = fmaf(x, 1.0f / 24.0f, 1.0f / 6.0f);
        p = fmaf(p, x, 0.5f);
        p = fmaf(p, x, 1.0f);
        p = fmaf(p, x, 1.0f);
        return p;
    }
    return __expf(x);
}

// ---------------- kernel 1: x fp32 -> fp16 ----------------
__global__ void xconv_kernel(const float4* __restrict__ x, uint2* __restrict__ xh) {
    int i = blockIdx.x * blockDim.x + threadIdx.x;
    float4 f = x[i];
    __half2 h0 = __floats2half2_rn(f.x, f.y);
    __half2 h1 = __floats2half2_rn(f.z, f.w);
    uint2 u;
    u.x = *reinterpret_cast<uint32_t*>(&h0);
    u.y = *reinterpret_cast<uint32_t*>(&h1);
    xh[i] = u;
}

// ---------------- kernel 2: fused sinkhorn (persistent, linear domain) ----
// E = exp(W/T);  iterate u' = sqrt(u/(E v)),  v' = sqrt(v/(E^T u));
// finally wh[i][j] = E[i][j] * u[i] * v[j]  (fp16).
__global__ void __launch_bounds__(STHR, 1) sinkhorn_fused_kernel(
    const float* __restrict__ w, __half* __restrict__ wh)
{
    __shared__ float sv[NSZ];        // v (all columns)
    __shared__ float su[ROWS_PER];   // old u (own rows)
    __shared__ float sR[ROWS_PER];   // row sums
    __shared__ float sws[32];        // warp partial sums

    const int b   = blockIdx.x;
    const int tid = threadIdx.x;
    const int wid = tid >> 5, lid = tid & 31;
    const int rb  = b * ROWS_PER;    // own row base (also own col base)

    // ---- phase 0: E = exp(w * 8), init u = v = 1 ----
    {
        const float4* wp = reinterpret_cast<const float4*>(w + (size_t)rb * NSZ);
        float4* ep = reinterpret_cast<float4*>(g_E + (size_t)rb * NSZ);
        const int nq = ROWS_PER * NSZ / 4;            // 2048 float4 per CTA
        for (int i = tid; i < nq; i += STHR) {
            float4 f = wp[i];
            float4 e;
            e.x = exp_mixed(f.x * 8.0f);
            e.y = exp_mixed(f.y * 8.0f);
            e.z = exp_mixed(f.z * 8.0f);
            e.w = exp_mixed(f.w * 8.0f);
            ep[i] = e;
        }
        if (tid < ROWS_PER) {
            g_u[rb + tid] = 1.0f;
            g_v[rb + tid] = 1.0f;
        }
    }
    grid_barrier();

    // ---- iterations ----
    for (int it = 0; it < N_ITER; it++) {
        // load fresh v (all) and own old u into smem
        #pragma unroll
        for (int i = tid; i < NSZ; i += STHR) sv[i] = g_v[i];
        if (tid < ROWS_PER) su[tid] = g_u[rb + tid];
        __syncthreads();

        // sweep 1: R_i = sum_j E_ij v_j   (warp pair per row, halves)
        {
            int row  = rb + (wid >> 1);
            int half = (wid & 1) * 512;
            const float* er = g_E + (size_t)row * NSZ + half;
            const float* vr = sv + half;
            float s = 0.f;
            #pragma unroll
            for (int k = 0; k < 16; k++)
                s = fmaf(er[lid + 32 * k], vr[lid + 32 * k], s);
            #pragma unroll
            for (int off = 16; off > 0; off >>= 1)
                s += __shfl_xor_sync(0xffffffffu, s, off);
            if (lid == 0) sws[wid] = s;
        }
        __syncthreads();
        if (tid < ROWS_PER) {
            float R = sws[2 * tid] + sws[2 * tid + 1];
            g_u[rb + tid] = sqrtf(su[tid] / R);       // new u (uses old u)
        }

        // sweep 2: column partials  cpart[b][j] = sum_{i in own} E_ij * u_i(old)
        {
            float c0 = 0.f, c1 = 0.f;
            const float* e0 = g_E + (size_t)rb * NSZ + tid;
            #pragma unroll
            for (int i = 0; i < ROWS_PER; i++) {
                float ui = su[i];
                c0 = fmaf(e0[(size_t)i * NSZ],       ui, c0);
                c1 = fmaf(e0[(size_t)i * NSZ + 512], ui, c1);
            }
            g_cpart[b][tid]       = c0;
            g_cpart[b][tid + 512] = c1;
        }
        grid_barrier();

        // phase B: reduce partials for own 8 columns, update v
        if (tid < ROWS_PER * 32) {
            int col  = rb + (tid >> 5);
            int lane = tid & 31;
            float c = 0.f;
            #pragma unroll
            for (int q = 0; q < SCTA / 32; q++)
                c += g_cpart[lane + 32 * q][col];
            #pragma unroll
            for (int off = 16; off > 0; off >>= 1)
                c += __shfl_xor_sync(0xffffffffu, c, off);
            if (lane == 0)
                g_v[col] = sqrtf(sv[col] / c);        // uses old v
        }
        grid_barrier();
    }

    // ---- final: wh[i][j] = E[i][j] * u_i * v_j (fp16) ----
    #pragma unroll
    for (int i = tid; i < NSZ; i += STHR) sv[i] = g_v[i];
    if (tid < ROWS_PER) su[tid] = g_u[rb + tid];
    __syncthreads();
    {
        int row  = rb + (wid >> 1);
        int half = (wid & 1) * 512;
        float ui = su[wid >> 1];
        const float2* er = reinterpret_cast<const float2*>(g_E + (size_t)row * NSZ + half);
        const float2* vr = reinterpret_cast<const float2*>(sv + half);
        __half2* wr = reinterpret_cast<__half2*>(wh + (size_t)row * NSZ + half);
        #pragma unroll
        for (int k = 0; k < 8; k++) {
            int idx = lid + 32 * k;
            float2 e = er[idx];
            float2 v2 = vr[idx];
            wr[idx] = __floats2half2_rn(e.x * ui * v2.x, e.y * ui * v2.y);
        }
    }
}

// ---------------- kernel 3: HMMA fp16 GEMM  y = x @ W^T ----------------
// A = g_xh [M, K] K-contig, B = g_wh [N, K] K-contig, out fp32 [M, N].
__device__ __forceinline__ void load_stage(uint32_t sbase, const __half* __restrict__ A,
                                           const __half* __restrict__ B,
                                           int m_base, int n_base, int kc, int tid) {
    const uint32_t sA = sbase, sB = sbase + A_BYTES;
    const __half* ga = A + (size_t)m_base * NSZ + kc * BK;
    const __half* gb = B + (size_t)n_base * NSZ + kc * BK;
    #pragma unroll
    for (int i = 0; i < 4; i++) {
        int id = tid + i * 256;
        int row = id >> 3, c = id & 7;
        cp_async16(sA + swz(row * ROWB + c * 16), ga + row * NSZ + c * 8);
    }
    #pragma unroll
    for (int i = 0; i < 4; i++) {
        int id = tid + i * 256;
        int row = id >> 3, c = id & 7;
        cp_async16(sB + swz(row * ROWB + c * 16), gb + row * NSZ + c * 8);
    }
}

__global__ void __launch_bounds__(256, 2) gemm_kernel(
    const __half* __restrict__ A, const __half* __restrict__ B,
    float* __restrict__ out)
{
    extern __shared__ __align__(1024) char smem[];
    const uint32_t sb = smem_u32(smem);
    const int tid = threadIdx.x;
    const int lane = tid & 31;
    const int w = tid >> 5;
    const int wm = w >> 2;          // 0..1  -> M offset wm*64
    const int wn = w & 3;           // 0..3  -> N offset wn*32
    const int n_base = blockIdx.x * BN;
    const int m_base = blockIdx.y * BM;

    float acc[4][4][4];
    #pragma unroll
    for (int i = 0; i < 4; i++)
        #pragma unroll
        for (int j = 0; j < 4; j++)
            #pragma unroll
            for (int q = 0; q < 4; q++) acc[i][j][q] = 0.f;

    const uint32_t aRow = (uint32_t)(wm * 64 + (lane & 15)) * ROWB + ((lane >> 4) * 16);
    const uint32_t bRow = (uint32_t)(wn * 32 + (lane & 7)) * ROWB + (((lane >> 3) & 1) * 16);

    load_stage(sb + 0 * STAGE_B, A, B, m_base, n_base, 0, tid);
    asm volatile("cp.async.commit_group;" ::: "memory");
    load_stage(sb + 1 * STAGE_B, A, B, m_base, n_base, 1, tid);
    asm volatile("cp.async.commit_group;" ::: "memory");

    int buf = 0;
    #pragma unroll 1
    for (int kc = 0; kc < NKC; kc++) {
        asm volatile("cp.async.wait_group 1;" ::: "memory");
        __syncthreads();

        if (kc + 2 < NKC) {
            int nb = buf + 2; if (nb >= STG) nb -= STG;
            load_stage(sb + nb * STAGE_B, A, B, m_base, n_base, kc + 2, tid);
        }
        asm volatile("cp.async.commit_group;" ::: "memory");

        const uint32_t sA = sb + buf * STAGE_B;
        const uint32_t sB = sA + A_BYTES;
        #pragma unroll
        for (int ks = 0; ks < 4; ks++) {
            uint32_t af[4][4], bf[4][2];
            #pragma unroll
            for (int mt = 0; mt < 4; mt++)
                ldsm_x4(af[mt], sA + swz(aRow + (uint32_t)mt * 16 * ROWB + ks * 32));
            #pragma unroll
            for (int nt = 0; nt < 4; nt++)
                ldsm_x2(bf[nt], sB + swz(bRow + (uint32_t)nt * 8 * ROWB + ks * 32));
            #pragma unroll
            for (int mt = 0; mt < 4; mt++)
                #pragma unroll
                for (int nt = 0; nt < 4; nt++)
                    mma16816(acc[mt][nt], af[mt], bf[nt]);
        }
        buf++; if (buf >= STG) buf = 0;
    }

    const int r0 = m_base + wm * 64 + (lane >> 2);
    const int c0 = n_base + wn * 32 + (lane & 3) * 2;
    #pragma unroll
    for (int mt = 0; mt < 4; mt++) {
        #pragma unroll
        for (int nt = 0; nt < 4; nt++) {
            float* p0 = out + (size_t)(r0 + mt * 16) * NSZ + c0 + nt * 8;
            float* p1 = out + (size_t)(r0 + mt * 16 + 8) * NSZ + c0 + nt * 8;
            *reinterpret_cast<float2*>(p0) = make_float2(acc[mt][nt][0], acc[mt][nt][1]);
            *reinterpret_cast<float2*>(p1) = make_float2(acc[mt][nt][2], acc[mt][nt][3]);
        }
    }
}

// ---------------- host ----------------
extern "C" void kernel_launch(void* const* d_in, const int* in_sizes, int n_in,
                              void* d_out, int out_size) {
    const float* x = (const float*)d_in[0];
    const float* w = (const float*)d_in[1];
    if (in_sizes[0] == NSZ * NSZ && in_sizes[1] != NSZ * NSZ) {  // defensive ordering
        x = (const float*)d_in[1];
        w = (const float*)d_in[0];
    }
    float* out = (float*)d_out;

    void* xh_ptr = nullptr;
    void* wh_ptr = nullptr;
    cudaGetSymbolAddress(&xh_ptr, g_xh);
    cudaGetSymbolAddress(&wh_ptr, g_wh);

    cudaFuncSetAttribute(gemm_kernel, cudaFuncAttributeMaxDynamicSharedMemorySize, SMEM_TOTAL);

    // 1) convert x to fp16
    xconv_kernel<<<(M_TOTAL * NSZ / 4) / 256, 256>>>((const float4*)x, (uint2*)xh_ptr);

    // 2) fused sinkhorn + fp16 W materialization (persistent, 1 launch)
    sinkhorn_fused_kernel<<<SCTA, STHR>>>(w, (__half*)wh_ptr);

    // 3) GEMM
    gemm_kernel<<<dim3(NSZ / BN, M_TOTAL / BM, 1), 256, SMEM_TOTAL>>>(
        (const __half*)xh_ptr, (const __half*)wh_ptr, out);
}

// round 6
// speedup vs baseline: 1.2004x; 1.0873x over previous
#include <cuda_runtime.h>
#include <cuda_fp16.h>
#include <cstdint>

// ---------------- problem constants ----------------
#define NSZ      1024
#define M_TOTAL  32768

// GEMM tiling
#define BM 128
#define BN 128
#define BK 64                       // halves per K chunk (128 bytes per smem row)
#define STG 3
#define NKC (NSZ / BK)              // 16 K-chunks
#define ROWB 128                    // bytes per smem row
#define A_BYTES (BM * ROWB)         // 16384
#define B_BYTES (BN * ROWB)         // 16384
#define STAGE_B (A_BYTES + B_BYTES) // 32768
#define SMEM_TOTAL (STG * STAGE_B)  // 98304

// fused pre-pass: 32 sinkhorn CTAs + 116 xconv CTAs, all co-resident
#define SK_CTA  32
#define TOT_CTA 148
#define THR     512
#define RPC     (NSZ / SK_CTA)      // 32 rows (and cols) per sinkhorn CTA
#define N_ITER  10

// ---------------- scratch (no allocation allowed) ----------------
__device__ __align__(1024) __half g_xh[(size_t)M_TOTAL * NSZ];   // 64 MiB fp16 x
__device__ __align__(1024) __half g_wh[NSZ * NSZ];               // 2 MiB fp16 W
__device__ __align__(1024) float  g_E [NSZ * NSZ];               // 4 MiB exp(W/T)
__device__ __align__(1024) float  g_ET[NSZ * NSZ];               // 4 MiB transpose
__device__ float g_u[NSZ];
__device__ float g_v[NSZ];
__device__ int          g_bar_cnt;
__device__ volatile int g_bar_gen;

// ---------------- helpers ----------------
__device__ __forceinline__ uint32_t smem_u32(const void* p) {
    uint32_t a;
    asm("{ .reg .u64 t; cvta.to.shared.u64 t, %1; cvt.u32.u64 %0, t; }" : "=r"(a) : "l"(p));
    return a;
}
__device__ __forceinline__ uint32_t swz(uint32_t o) {       // 128B swizzle
    return o ^ ((o >> 3) & 0x70);
}
__device__ __forceinline__ void cp_async16(uint32_t saddr, const void* gaddr) {
    asm volatile("cp.async.cg.shared.global [%0], [%1], 16;" :: "r"(saddr), "l"(gaddr));
}
__device__ __forceinline__ void ldsm_x4(uint32_t* r, uint32_t addr) {
    asm volatile("ldmatrix.sync.aligned.m8n8.x4.shared.b16 {%0,%1,%2,%3}, [%4];"
                 : "=r"(r[0]), "=r"(r[1]), "=r"(r[2]), "=r"(r[3]) : "r"(addr));
}
__device__ __forceinline__ void ldsm_x2(uint32_t* r, uint32_t addr) {
    asm volatile("ldmatrix.sync.aligned.m8n8.x2.shared.b16 {%0,%1}, [%2];"
                 : "=r"(r[0]), "=r"(r[1]) : "r"(addr));
}
__device__ __forceinline__ void mma16816(float* d, const uint32_t* a, const uint32_t* b) {
    asm volatile(
        "mma.sync.aligned.m16n8k16.row.col.f32.f16.f16.f32 "
        "{%0,%1,%2,%3}, {%4,%5,%6,%7}, {%8,%9}, {%0,%1,%2,%3};"
        : "+f"(d[0]), "+f"(d[1]), "+f"(d[2]), "+f"(d[3])
        : "r"(a[0]), "r"(a[1]), "r"(a[2]), "r"(a[3]), "r"(b[0]), "r"(b[1]));
}

// grid-wide barrier over the SK_CTA sinkhorn CTAs only.
// __threadfence (gpu scope) emits CCTL.IVALL so post-barrier loads see
// other CTAs' writes.
__device__ __forceinline__ void sk_barrier() {
    __syncthreads();
    if (threadIdx.x == 0) {
        int gen = g_bar_gen;
        __threadfence();
        if (atomicAdd(&g_bar_cnt, 1) == SK_CTA - 1) {
            atomicExch(&g_bar_cnt, 0);
            __threadfence();
            g_bar_gen = gen + 1;
        } else {
            while (g_bar_gen == gen) { __nanosleep(64); }
        }
        __threadfence();
    }
    __syncthreads();
}

// exp with cheap polynomial for tiny args (off-diagonal entries ~1e-4)
__device__ __forceinline__ float exp_mixed(float x) {
    if (fabsf(x) < 0.125f) {
        float p = fmaf(x, 1.0f / 24.0f, 1.0f / 6.0f);
        p = fmaf(p, x, 0.5f);
        p = fmaf(p, x, 1.0f);
        p = fmaf(p, x, 1.0f);
        return p;
    }
    return __expf(x);
}

// ---------------- kernel 1: fused pre-pass -----------------------------
// CTAs [0, SK_CTA): linear-domain sinkhorn on E = exp(W/T):
//     u' = sqrt(u / (E v)),  v' = sqrt(v / (E^T u)),  10 iters,
//     then wh = E * u ⊗ v in fp16.
// CTAs [SK_CTA, TOT_CTA): convert x fp32 -> fp16 (grid-stride), overlapped.
__global__ void __launch_bounds__(THR, 1) fused_pre_kernel(
    const float4* __restrict__ x, const float* __restrict__ w,
    __half* __restrict__ wh, uint2* __restrict__ xh)
{
    const int tid = threadIdx.x;

    if (blockIdx.x >= SK_CTA) {
        // ---------------- xconv part ----------------
        const int total = M_TOTAL * NSZ / 4;
        const int stride = (TOT_CTA - SK_CTA) * THR;
        int i = (blockIdx.x - SK_CTA) * THR + tid;
        #pragma unroll 4
        for (; i < total; i += stride) {
            float4 f = x[i];
            __half2 h0 = __floats2half2_rn(f.x, f.y);
            __half2 h1 = __floats2half2_rn(f.z, f.w);
            uint2 u;
            u.x = *reinterpret_cast<uint32_t*>(&h0);
            u.y = *reinterpret_cast<uint32_t*>(&h1);
            xh[i] = u;
        }
        return;
    }

    // ---------------- sinkhorn part ----------------
    __shared__ __align__(16) float sE[8 * 1032];   // transpose staging (33 KB)
    __shared__ __align__(16) float su[NSZ];
    __shared__ __align__(16) float sv[NSZ];

    const int b   = blockIdx.x;
    const int wid = tid >> 5, lid = tid & 31;
    const int rb  = b * RPC;                      // own rows / own cols

    // ---- phase 0: E = exp(w*8), ET = E^T, u = v = 1 ----
    #pragma unroll 1
    for (int g = 0; g < RPC / 8; g++) {
        const int r0 = rb + 8 * g;
        const float4* wp = reinterpret_cast<const float4*>(w + (size_t)r0 * NSZ);
        float4* ep = reinterpret_cast<float4*>(g_E + (size_t)r0 * NSZ);
        for (int i = tid; i < 8 * NSZ / 4; i += THR) {
            float4 f = wp[i];
            float4 e;
            e.x = exp_mixed(f.x * 8.0f);
            e.y = exp_mixed(f.y * 8.0f);
            e.z = exp_mixed(f.z * 8.0f);
            e.w = exp_mixed(f.w * 8.0f);
            ep[i] = e;
            int row = i >> 8, c4 = i & 255;
            reinterpret_cast<float4*>(sE + row * 1032)[c4] = e;
        }
        __syncthreads();
        for (int j = tid; j < NSZ; j += THR) {
            float4 a = make_float4(sE[0 * 1032 + j], sE[1 * 1032 + j],
                                   sE[2 * 1032 + j], sE[3 * 1032 + j]);
            float4 c = make_float4(sE[4 * 1032 + j], sE[5 * 1032 + j],
                                   sE[6 * 1032 + j], sE[7 * 1032 + j]);
            float4* tp = reinterpret_cast<float4*>(g_ET + (size_t)j * NSZ + r0);
            tp[0] = a; tp[1] = c;
        }
        __syncthreads();
    }
    if (tid < RPC) {
        g_u[rb + tid] = 1.0f;
        g_v[rb + tid] = 1.0f;
    }
    sk_barrier();

    // ---- iterations: one barrier each ----
    for (int it = 0; it < N_ITER; it++) {
        for (int i = tid; i < NSZ; i += THR) { su[i] = g_u[i]; sv[i] = g_v[i]; }
        __syncthreads();

        // u' for own rows (2 rows per warp)
        #pragma unroll
        for (int rr = 0; rr < 2; rr++) {
            int row = rb + 2 * wid + rr;
            const float4* er = reinterpret_cast<const float4*>(g_E + (size_t)row * NSZ);
            const float4* vr = reinterpret_cast<const float4*>(sv);
            float s = 0.f;
            #pragma unroll
            for (int k = 0; k < 8; k++) {
                float4 e = er[lid + 32 * k];
                float4 v4 = vr[lid + 32 * k];
                s = fmaf(e.x, v4.x, s); s = fmaf(e.y, v4.y, s);
                s = fmaf(e.z, v4.z, s); s = fmaf(e.w, v4.w, s);
            }
            #pragma unroll
            for (int off = 16; off > 0; off >>= 1)
                s += __shfl_xor_sync(0xffffffffu, s, off);
            if (lid == 0) g_u[row] = sqrtf(su[row] / s);
        }

        // v' for own cols via ET rows (2 per warp), uses OLD u from smem
        #pragma unroll
        for (int rr = 0; rr < 2; rr++) {
            int col = rb + 2 * wid + rr;
            const float4* er = reinterpret_cast<const float4*>(g_ET + (size_t)col * NSZ);
            const float4* ur = reinterpret_cast<const float4*>(su);
            float s = 0.f;
            #pragma unroll
            for (int k = 0; k < 8; k++) {
                float4 e = er[lid + 32 * k];
                float4 u4 = ur[lid + 32 * k];
                s = fmaf(e.x, u4.x, s); s = fmaf(e.y, u4.y, s);
                s = fmaf(e.z, u4.z, s); s = fmaf(e.w, u4.w, s);
            }
            #pragma unroll
            for (int off = 16; off > 0; off >>= 1)
                s += __shfl_xor_sync(0xffffffffu, s, off);
            if (lid == 0) g_v[col] = sqrtf(sv[col] / s);
        }
        sk_barrier();
    }

    // ---- final: wh[i][j] = E[i][j] * u_i * v_j (fp16) ----
    for (int i = tid; i < NSZ; i += THR) sv[i] = g_v[i];
    __syncthreads();
    #pragma unroll
    for (int rr = 0; rr < 2; rr++) {
        int row = rb + 2 * wid + rr;
        float ui = g_u[row];
        const float4* er = reinterpret_cast<const float4*>(g_E + (size_t)row * NSZ);
        const float4* vr = reinterpret_cast<const float4*>(sv);
        uint2* wr = reinterpret_cast<uint2*>(wh + (size_t)row * NSZ);
        #pragma unroll
        for (int k = 0; k < 8; k++) {
            int idx = lid + 32 * k;
            float4 e = er[idx];
            float4 v4 = vr[idx];
            __half2 h0 = __floats2half2_rn(e.x * ui * v4.x, e.y * ui * v4.y);
            __half2 h1 = __floats2half2_rn(e.z * ui * v4.z, e.w * ui * v4.w);
            uint2 o;
            o.x = *reinterpret_cast<uint32_t*>(&h0);
            o.y = *reinterpret_cast<uint32_t*>(&h1);
            wr[idx] = o;
        }
    }
}

// ---------------- kernel 2: HMMA fp16 GEMM  y = x @ W^T ----------------
__device__ __forceinline__ void load_stage(uint32_t sbase, const __half* __restrict__ A,
                                           const __half* __restrict__ B,
                                           int m_base, int n_base, int kc, int tid) {
    const uint32_t sA = sbase, sB = sbase + A_BYTES;
    const __half* ga = A + (size_t)m_base * NSZ + kc * BK;
    const __half* gb = B + (size_t)n_base * NSZ + kc * BK;
    #pragma unroll
    for (int i = 0; i < 4; i++) {
        int id = tid + i * 256;
        int row = id >> 3, c = id & 7;
        cp_async16(sA + swz(row * ROWB + c * 16), ga + row * NSZ + c * 8);
    }
    #pragma unroll
    for (int i = 0; i < 4; i++) {
        int id = tid + i * 256;
        int row = id >> 3, c = id & 7;
        cp_async16(sB + swz(row * ROWB + c * 16), gb + row * NSZ + c * 8);
    }
}

__global__ void __launch_bounds__(256, 2) gemm_kernel(
    const __half* __restrict__ A, const __half* __restrict__ B,
    float* __restrict__ out)
{
    extern __shared__ __align__(1024) char smem[];
    const uint32_t sb = smem_u32(smem);
    const int tid = threadIdx.x;
    const int lane = tid & 31;
    const int w = tid >> 5;
    const int wm = w >> 2;
    const int wn = w & 3;
    const int n_base = blockIdx.x * BN;
    const int m_base = blockIdx.y * BM;

    float acc[4][4][4];
    #pragma unroll
    for (int i = 0; i < 4; i++)
        #pragma unroll
        for (int j = 0; j < 4; j++)
            #pragma unroll
            for (int q = 0; q < 4; q++) acc[i][j][q] = 0.f;

    const uint32_t aRow = (uint32_t)(wm * 64 + (lane & 15)) * ROWB + ((lane >> 4) * 16);
    const uint32_t bRow = (uint32_t)(wn * 32 + (lane & 7)) * ROWB + (((lane >> 3) & 1) * 16);

    load_stage(sb + 0 * STAGE_B, A, B, m_base, n_base, 0, tid);
    asm volatile("cp.async.commit_group;" ::: "memory");
    load_stage(sb + 1 * STAGE_B, A, B, m_base, n_base, 1, tid);
    asm volatile("cp.async.commit_group;" ::: "memory");

    int buf = 0;
    #pragma unroll 1
    for (int kc = 0; kc < NKC; kc++) {
        asm volatile("cp.async.wait_group 1;" ::: "memory");
        __syncthreads();

        if (kc + 2 < NKC) {
            int nb = buf + 2; if (nb >= STG) nb -= STG;
            load_stage(sb + nb * STAGE_B, A, B, m_base, n_base, kc + 2, tid);
        }
        asm volatile("cp.async.commit_group;" ::: "memory");

        const uint32_t sA = sb + buf * STAGE_B;
        const uint32_t sB = sA + A_BYTES;
        #pragma unroll
        for (int ks = 0; ks < 4; ks++) {
            uint32_t af[4][4], bf[4][2];
            #pragma unroll
            for (int mt = 0; mt < 4; mt++)
                ldsm_x4(af[mt], sA + swz(aRow + (uint32_t)mt * 16 * ROWB + ks * 32));
            #pragma unroll
            for (int nt = 0; nt < 4; nt++)
                ldsm_x2(bf[nt], sB + swz(bRow + (uint32_t)nt * 8 * ROWB + ks * 32));
            #pragma unroll
            for (int mt = 0; mt < 4; mt++)
                #pragma unroll
                for (int nt = 0; nt < 4; nt++)
                    mma16816(acc[mt][nt], af[mt], bf[nt]);
        }
        buf++; if (buf >= STG) buf = 0;
    }

    const int r0 = m_base + wm * 64 + (lane >> 2);
    const int c0 = n_base + wn * 32 + (lane & 3) * 2;
    #pragma unroll
    for (int mt = 0; mt < 4; mt++) {
        #pragma unroll
        for (int nt = 0; nt < 4; nt++) {
            float* p0 = out + (size_t)(r0 + mt * 16) * NSZ + c0 + nt * 8;
            float* p1 = out + (size_t)(r0 + mt * 16 + 8) * NSZ + c0 + nt * 8;
            *reinterpret_cast<float2*>(p0) = make_float2(acc[mt][nt][0], acc[mt][nt][1]);
            *reinterpret_cast<float2*>(p1) = make_float2(acc[mt][nt][2], acc[mt][nt][3]);
        }
    }
}

// ---------------- host ----------------
extern "C" void kernel_launch(void* const* d_in, const int* in_sizes, int n_in,
                              void* d_out, int out_size) {
    const float* x = (const float*)d_in[0];
    const float* w = (const float*)d_in[1];
    if (in_sizes[0] == NSZ * NSZ && in_sizes[1] != NSZ * NSZ) {  // defensive ordering
        x = (const float*)d_in[1];
        w = (const float*)d_in[0];
    }
    float* out = (float*)d_out;

    void* xh_ptr = nullptr;
    void* wh_ptr = nullptr;
    cudaGetSymbolAddress(&xh_ptr, g_xh);
    cudaGetSymbolAddress(&wh_ptr, g_wh);

    cudaFuncSetAttribute(gemm_kernel, cudaFuncAttributeMaxDynamicSharedMemorySize, SMEM_TOTAL);

    // 1) fused: sinkhorn (CTAs 0..31) + x fp32->fp16 (CTAs 32..147)
    fused_pre_kernel<<<TOT_CTA, THR>>>((const float4*)x, w,
                                       (__half*)wh_ptr, (uint2*)xh_ptr);

    // 2) GEMM
    gemm_kernel<<<dim3(NSZ / BN, M_TOTAL / BM, 1), 256, SMEM_TOTAL>>>(
        (const __half*)xh_ptr, (const __half*)wh_ptr, out);
}

// round 7
// speedup vs baseline: 1.3881x; 1.1563x over previous
#include <cuda_runtime.h>
#include <cuda_fp16.h>
#include <cstdint>

// ---------------- problem constants ----------------
#define NSZ      1024
#define M_TOTAL  32768

// GEMM tiling: CTA 128x128, 4 warps of 64x64
#define BM 128
#define BN 128
#define BK 64                       // halves per K chunk (128 bytes per smem row)
#define STG 3
#define NKC (NSZ / BK)              // 16 K-chunks
#define ROWB 128                    // bytes per smem row
#define A_BYTES (BM * ROWB)         // 16384
#define B_BYTES (BN * ROWB)         // 16384
#define STAGE_B (A_BYTES + B_BYTES) // 32768
#define SMEM_TOTAL (STG * STAGE_B)  // 98304
#define GTHR 128

// fused pre-pass: 64 sinkhorn CTAs + 84 xconv CTAs, all co-resident
#define SK_CTA  64
#define TOT_CTA 148
#define XC_CTA  (TOT_CTA - SK_CTA)  // 84
#define THR     512
#define RPC     (NSZ / SK_CTA)      // 16 rows (and cols) per sinkhorn CTA
#define N_ITER  10
#define TOTAL4  (M_TOTAL * NSZ / 4) // 8388608 float4s of x
#define XSPLIT  ((TOTAL4 / 100) * 84)

// ---------------- scratch (no allocation allowed) ----------------
__device__ __align__(1024) __half g_xh[(size_t)M_TOTAL * NSZ];   // 64 MiB fp16 x
__device__ __align__(1024) __half g_wh[NSZ * NSZ];               // 2 MiB fp16 W
__device__ __align__(1024) float  g_E [NSZ * NSZ];               // 4 MiB exp(W/T)
__device__ __align__(1024) float  g_ET[NSZ * NSZ];               // 4 MiB transpose
__device__ float g_u[NSZ];
__device__ float g_v[NSZ];
__device__ int          g_bar_cnt;
__device__ volatile int g_bar_gen;

// ---------------- helpers ----------------
__device__ __forceinline__ uint32_t smem_u32(const void* p) {
    uint32_t a;
    asm("{ .reg .u64 t; cvta.to.shared.u64 t, %1; cvt.u32.u64 %0, t; }" : "=r"(a) : "l"(p));
    return a;
}
__device__ __forceinline__ uint32_t swz(uint32_t o) {       // 128B swizzle
    return o ^ ((o >> 3) & 0x70);
}
__device__ __forceinline__ void cp_async16(uint32_t saddr, const void* gaddr) {
    asm volatile("cp.async.cg.shared.global [%0], [%1], 16;" :: "r"(saddr), "l"(gaddr));
}
__device__ __forceinline__ void ldsm_x4(uint32_t* r, uint32_t addr) {
    asm volatile("ldmatrix.sync.aligned.m8n8.x4.shared.b16 {%0,%1,%2,%3}, [%4];"
                 : "=r"(r[0]), "=r"(r[1]), "=r"(r[2]), "=r"(r[3]) : "r"(addr));
}
__device__ __forceinline__ void mma16816(float* d, const uint32_t* a, const uint32_t* b) {
    asm volatile(
        "mma.sync.aligned.m16n8k16.row.col.f32.f16.f16.f32 "
        "{%0,%1,%2,%3}, {%4,%5,%6,%7}, {%8,%9}, {%0,%1,%2,%3};"
        : "+f"(d[0]), "+f"(d[1]), "+f"(d[2]), "+f"(d[3])
        : "r"(a[0]), "r"(a[1]), "r"(a[2]), "r"(a[3]), "r"(b[0]), "r"(b[1]));
}

// grid-wide barrier over the SK_CTA sinkhorn CTAs only.
__device__ __forceinline__ void sk_barrier() {
    __syncthreads();
    if (threadIdx.x == 0) {
        int gen = g_bar_gen;
        __threadfence();
        if (atomicAdd(&g_bar_cnt, 1) == SK_CTA - 1) {
            atomicExch(&g_bar_cnt, 0);
            __threadfence();
            g_bar_gen = gen + 1;
        } else {
            while (g_bar_gen == gen) { __nanosleep(64); }
        }
        __threadfence();
    }
    __syncthreads();
}

// exp with cheap polynomial for tiny args (off-diagonal entries ~1e-4)
__device__ __forceinline__ float exp_mixed(float x) {
    if (fabsf(x) < 0.125f) {
        float p = fmaf(x, 1.0f / 24.0f, 1.0f / 6.0f);
        p = fmaf(p, x, 0.5f);
        p = fmaf(p, x, 1.0f);
        p = fmaf(p, x, 1.0f);
        return p;
    }
    return __expf(x);
}

__device__ __forceinline__ void xconv_range(const float4* __restrict__ x,
                                            uint2* __restrict__ xh,
                                            int start, int end, int stride) {
    #pragma unroll 4
    for (int i = start; i < end; i += stride) {
        float4 f = x[i];
        __half2 h0 = __floats2half2_rn(f.x, f.y);
        __half2 h1 = __floats2half2_rn(f.z, f.w);
        uint2 u;
        u.x = *reinterpret_cast<uint32_t*>(&h0);
        u.y = *reinterpret_cast<uint32_t*>(&h1);
        xh[i] = u;
    }
}

// ---------------- kernel 1: fused pre-pass -----------------------------
// CTAs [0, SK_CTA): linear-domain sinkhorn on E = exp(W/T):
//     u' = sqrt(u / (E v)),  v' = sqrt(v / (E^T u)),  10 iters,
//     then wh = E * u ⊗ v (fp16), then tail 16% of xconv.
// CTAs [SK_CTA, TOT_CTA): convert first 84% of x fp32 -> fp16.
__global__ void __launch_bounds__(THR, 1) fused_pre_kernel(
    const float4* __restrict__ x, const float* __restrict__ w,
    __half* __restrict__ wh, uint2* __restrict__ xh)
{
    const int tid = threadIdx.x;

    if (blockIdx.x >= SK_CTA) {
        // ---------------- dedicated xconv: [0, XSPLIT) ----------------
        xconv_range(x, xh, (blockIdx.x - SK_CTA) * THR + tid, XSPLIT, XC_CTA * THR);
        return;
    }

    // ---------------- sinkhorn part ----------------
    __shared__ __align__(16) float sE[8 * 1032];   // transpose staging (33 KB)
    __shared__ __align__(16) float su[NSZ];
    __shared__ __align__(16) float sv[NSZ];

    const int b   = blockIdx.x;
    const int wid = tid >> 5, lid = tid & 31;
    const int rb  = b * RPC;                      // own rows / own cols

    // ---- phase 0: E = exp(w*8), ET = E^T, u = v = 1 ----
    #pragma unroll 1
    for (int g = 0; g < RPC / 8; g++) {
        const int r0 = rb + 8 * g;
        const float4* wp = reinterpret_cast<const float4*>(w + (size_t)r0 * NSZ);
        float4* ep = reinterpret_cast<float4*>(g_E + (size_t)r0 * NSZ);
        for (int i = tid; i < 8 * NSZ / 4; i += THR) {
            float4 f = wp[i];
            float4 e;
            e.x = exp_mixed(f.x * 8.0f);
            e.y = exp_mixed(f.y * 8.0f);
            e.z = exp_mixed(f.z * 8.0f);
            e.w = exp_mixed(f.w * 8.0f);
            ep[i] = e;
            int row = i >> 8, c4 = i & 255;
            reinterpret_cast<float4*>(sE + row * 1032)[c4] = e;
        }
        __syncthreads();
        for (int j = tid; j < NSZ; j += THR) {
            float4 a = make_float4(sE[0 * 1032 + j], sE[1 * 1032 + j],
                                   sE[2 * 1032 + j], sE[3 * 1032 + j]);
            float4 c = make_float4(sE[4 * 1032 + j], sE[5 * 1032 + j],
                                   sE[6 * 1032 + j], sE[7 * 1032 + j]);
            float4* tp = reinterpret_cast<float4*>(g_ET + (size_t)j * NSZ + r0);
            tp[0] = a; tp[1] = c;
        }
        __syncthreads();
    }
    if (tid < RPC) {
        g_u[rb + tid] = 1.0f;
        g_v[rb + tid] = 1.0f;
    }
    sk_barrier();

    // ---- iterations: one barrier each; 1 row + 1 col per warp, interleaved ----
    for (int it = 0; it < N_ITER; it++) {
        for (int i = tid; i < NSZ; i += THR) { su[i] = g_u[i]; sv[i] = g_v[i]; }
        __syncthreads();

        const int idx = rb + wid;   // own row (in E) == own col (row in ET)
        const float4* er = reinterpret_cast<const float4*>(g_E  + (size_t)idx * NSZ);
        const float4* tr = reinterpret_cast<const float4*>(g_ET + (size_t)idx * NSZ);
        const float4* vr = reinterpret_cast<const float4*>(sv);
        const float4* ur = reinterpret_cast<const float4*>(su);
        float s_u = 0.f, s_v = 0.f;
        #pragma unroll
        for (int k = 0; k < 8; k++) {
            float4 e  = er[lid + 32 * k];
            float4 t  = tr[lid + 32 * k];
            float4 v4 = vr[lid + 32 * k];
            float4 u4 = ur[lid + 32 * k];
            s_u = fmaf(e.x, v4.x, s_u); s_u = fmaf(e.y, v4.y, s_u);
            s_u = fmaf(e.z, v4.z, s_u); s_u = fmaf(e.w, v4.w, s_u);
            s_v = fmaf(t.x, u4.x, s_v); s_v = fmaf(t.y, u4.y, s_v);
            s_v = fmaf(t.z, u4.z, s_v); s_v = fmaf(t.w, u4.w, s_v);
        }
        #pragma unroll
        for (int off = 16; off > 0; off >>= 1) {
            s_u += __shfl_xor_sync(0xffffffffu, s_u, off);
            s_v += __shfl_xor_sync(0xffffffffu, s_v, off);
        }
        if (lid == 0) {
            g_u[idx] = sqrtf(su[idx] / s_u);
            g_v[idx] = sqrtf(sv[idx] / s_v);
        }
        sk_barrier();
    }

    // ---- final: wh[i][j] = E[i][j] * u_i * v_j (fp16), 1 row per warp ----
    for (int i = tid; i < NSZ; i += THR) sv[i] = g_v[i];
    __syncthreads();
    {
        int row = rb + wid;
        float ui = g_u[row];
        const float4* er = reinterpret_cast<const float4*>(g_E + (size_t)row * NSZ);
        const float4* vr = reinterpret_cast<const float4*>(sv);
        uint2* wr = reinterpret_cast<uint2*>(wh + (size_t)row * NSZ);
        #pragma unroll
        for (int k = 0; k < 8; k++) {
            int idx = lid + 32 * k;
            float4 e = er[idx];
            float4 v4 = vr[idx];
            __half2 h0 = __floats2half2_rn(e.x * ui * v4.x, e.y * ui * v4.y);
            __half2 h1 = __floats2half2_rn(e.z * ui * v4.z, e.w * ui * v4.w);
            uint2 o;
            o.x = *reinterpret_cast<uint32_t*>(&h0);
            o.y = *reinterpret_cast<uint32_t*>(&h1);
            wr[idx] = o;
        }
    }

    // ---- tail 16% of xconv ----
    xconv_range(x, xh, XSPLIT + b * THR + tid, TOTAL4, SK_CTA * THR);
}

// ---------------- kernel 2: HMMA fp16 GEMM  y = x @ W^T ----------------
// A = g_xh [M, K] K-contig, B = g_wh [N, K] K-contig, out fp32 [M, N].
// 128 threads, 4 warps (2x2), warp tile 64x64.
__device__ __forceinline__ void load_stage(uint32_t sbase, const __half* __restrict__ A,
                                           const __half* __restrict__ B,
                                           int m_base, int n_base, int kc, int tid) {
    const uint32_t sA = sbase, sB = sbase + A_BYTES;
    const __half* ga = A + (size_t)m_base * NSZ + kc * BK;
    const __half* gb = B + (size_t)n_base * NSZ + kc * BK;
    #pragma unroll
    for (int i = 0; i < 8; i++) {
        int id = tid + i * GTHR;
        int row = id >> 3, c = id & 7;
        cp_async16(sA + swz(row * ROWB + c * 16), ga + row * NSZ + c * 8);
    }
    #pragma unroll
    for (int i = 0; i < 8; i++) {
        int id = tid + i * GTHR;
        int row = id >> 3, c = id & 7;
        cp_async16(sB + swz(row * ROWB + c * 16), gb + row * NSZ + c * 8);
    }
}

__global__ void __launch_bounds__(GTHR, 2) gemm_kernel(
    const __half* __restrict__ A, const __half* __restrict__ B,
    float* __restrict__ out)
{
    extern __shared__ __align__(1024) char smem[];
    const uint32_t sb = smem_u32(smem);
    const int tid = threadIdx.x;
    const int lane = tid & 31;
    const int w = tid >> 5;
    const int wm = w >> 1;          // 0..1 -> M offset wm*64
    const int wn = w & 1;           // 0..1 -> N offset wn*64
    const int n_base = blockIdx.x * BN;
    const int m_base = blockIdx.y * BM;

    float acc[4][8][4];
    #pragma unroll
    for (int i = 0; i < 4; i++)
        #pragma unroll
        for (int j = 0; j < 8; j++)
            #pragma unroll
            for (int q = 0; q < 4; q++) acc[i][j][q] = 0.f;

    // per-lane ldmatrix byte offsets (pre-swizzle)
    const uint32_t aRow = (uint32_t)(wm * 64 + (lane & 15)) * ROWB + ((lane >> 4) * 16);
    // B x4 #p: lanes 0-7 -> (nt=2p,k0), 8-15 -> (nt=2p,k1), 16-23 -> (nt=2p+1,k0), 24-31 -> (nt=2p+1,k1)
    const uint32_t bRow = (uint32_t)(wn * 64 + ((lane >> 4) * 8) + (lane & 7)) * ROWB
                        + (((lane >> 3) & 1) * 16);

    load_stage(sb + 0 * STAGE_B, A, B, m_base, n_base, 0, tid);
    asm volatile("cp.async.commit_group;" ::: "memory");
    load_stage(sb + 1 * STAGE_B, A, B, m_base, n_base, 1, tid);
    asm volatile("cp.async.commit_group;" ::: "memory");

    int buf = 0;
    #pragma unroll 1
    for (int kc = 0; kc < NKC; kc++) {
        asm volatile("cp.async.wait_group 1;" ::: "memory");
        __syncthreads();

        if (kc + 2 < NKC) {
            int nb = buf + 2; if (nb >= STG) nb -= STG;
            load_stage(sb + nb * STAGE_B, A, B, m_base, n_base, kc + 2, tid);
        }
        asm volatile("cp.async.commit_group;" ::: "memory");

        const uint32_t sA = sb + buf * STAGE_B;
        const uint32_t sB = sA + A_BYTES;
        #pragma unroll
        for (int ks = 0; ks < 4; ks++) {
            uint32_t af[4][4], bf[4][4];
            #pragma unroll
            for (int mt = 0; mt < 4; mt++)
                ldsm_x4(af[mt], sA + swz(aRow + (uint32_t)mt * 16 * ROWB + ks * 32));
            #pragma unroll
            for (int p = 0; p < 4; p++)
                ldsm_x4(bf[p], sB + swz(bRow + (uint32_t)p * 16 * ROWB + ks * 32));
            #pragma unroll
            for (int mt = 0; mt < 4; mt++)
                #pragma unroll
                for (int nt = 0; nt < 8; nt++)
                    mma16816(acc[mt][nt], af[mt], &bf[nt >> 1][(nt & 1) * 2]);
        }
        buf++; if (buf >= STG) buf = 0;
    }

    // epilogue: direct fp32 stores
    const int r0 = m_base + wm * 64 + (lane >> 2);
    const int c0 = n_base + wn * 64 + (lane & 3) * 2;
    #pragma unroll
    for (int mt = 0; mt < 4; mt++) {
        #pragma unroll
        for (int nt = 0; nt < 8; nt++) {
            float* p0 = out + (size_t)(r0 + mt * 16) * NSZ + c0 + nt * 8;
            float* p1 = out + (size_t)(r0 + mt * 16 + 8) * NSZ + c0 + nt * 8;
            *reinterpret_cast<float2*>(p0) = make_float2(acc[mt][nt][0], acc[mt][nt][1]);
            *reinterpret_cast<float2*>(p1) = make_float2(acc[mt][nt][2], acc[mt][nt][3]);
        }
    }
}

// ---------------- host ----------------
extern "C" void kernel_launch(void* const* d_in, const int* in_sizes, int n_in,
                              void* d_out, int out_size) {
    const float* x = (const float*)d_in[0];
    const float* w = (const float*)d_in[1];
    if (in_sizes[0] == NSZ * NSZ && in_sizes[1] != NSZ * NSZ) {  // defensive ordering
        x = (const float*)d_in[1];
        w = (const float*)d_in[0];
    }
    float* out = (float*)d_out;

    void* xh_ptr = nullptr;
    void* wh_ptr = nullptr;
    cudaGetSymbolAddress(&xh_ptr, g_xh);
    cudaGetSymbolAddress(&wh_ptr, g_wh);

    cudaFuncSetAttribute(gemm_kernel, cudaFuncAttributeMaxDynamicSharedMemorySize, SMEM_TOTAL);

    // 1) fused: sinkhorn (CTAs 0..63) + x fp32->fp16 (CTAs 64..147 + tail)
    fused_pre_kernel<<<TOT_CTA, THR>>>((const float4*)x, w,
                                       (__half*)wh_ptr, (uint2*)xh_ptr);

    // 2) GEMM
    gemm_kernel<<<dim3(NSZ / BN, M_TOTAL / BM, 1), GTHR, SMEM_TOTAL>>>(
        (const __half*)xh_ptr, (const __half*)wh_ptr, out);
}